// round 1
// baseline (speedup 1.0000x reference)
#include <cuda_runtime.h>
#include <cuda_bf16.h>
#include <math.h>

// Problem constants (fixed shapes per reference)
#define NN 100000
#define EE 3200000
#define IN_DIM 512
#define H1 64
#define H2 32
#define H3 16
#define OUTD 40
#define BN_EPS 1e-5f

// ---------------- scratch (device globals: allocation-free) ----------------
__device__ float g_sup1[NN * H1];
__device__ float g_h1  [NN * H1];
__device__ float g_sup2[NN * H2];
__device__ float g_h2  [NN * H2];
__device__ float g_sup3[NN * H3];
__device__ float g_h3  [NN * H3];
__device__ float g_sup4[NN * OUTD];
__device__ int   g_rowptr[NN + 1];
__device__ float g_stats[128];   // [0..63]=sum, [64..127]=sumsq

// ---------------- CSR build (edge_row is sorted) ----------------
__global__ void build_rowptr_kernel(const int* __restrict__ row, int n, int e) {
    int i = blockIdx.x * blockDim.x + threadIdx.x;
    if (i >= e) return;
    int r = row[i];
    int prev = (i == 0) ? -1 : row[i - 1];
    for (int q = prev + 1; q <= r; q++) g_rowptr[q] = i;
    if (i == e - 1) {
        for (int q = r + 1; q <= n; q++) g_rowptr[q] = e;
    }
}

// ---------------- big GEMM: C[n x 64] = A[n x 512] @ B[512 x 64] ----------------
// BM=64, BN=64, BK=32, 256 threads, 4x4 micro-tile.
__global__ __launch_bounds__(256) void gemm512x64_kernel(
    const float* __restrict__ A, const float* __restrict__ B,
    float* __restrict__ C, int n)
{
    __shared__ __align__(16) float As[32][68];  // [k][row], pad 68 for banks, 272B row = 16B aligned
    __shared__ __align__(16) float Bs[32][64];  // [k][col]

    int tid = threadIdx.x;
    int tx = tid & 15;        // 0..15 -> col group
    int ty = tid >> 4;        // 0..15 -> row group
    int rowBase = blockIdx.x * 64;

    int ar  = tid >> 3;       // 0..31  (A load row)
    int ac4 = tid & 7;        // 0..7   (A load float4 index along k)
    int bk  = tid >> 4;       // 0..15  (B load k)
    int bn4 = tid & 15;       // 0..15  (B load float4 col)

    float acc[4][4] = {};

    for (int k0 = 0; k0 < IN_DIM; k0 += 32) {
        // load A tile (transposed into smem)
        #pragma unroll
        for (int rr = 0; rr < 2; rr++) {
            int r = ar + rr * 32;
            int grow = rowBase + r;
            float4 v = make_float4(0.f, 0.f, 0.f, 0.f);
            if (grow < n)
                v = *reinterpret_cast<const float4*>(A + (size_t)grow * IN_DIM + k0 + ac4 * 4);
            As[ac4 * 4 + 0][r] = v.x;
            As[ac4 * 4 + 1][r] = v.y;
            As[ac4 * 4 + 2][r] = v.z;
            As[ac4 * 4 + 3][r] = v.w;
        }
        // load B tile
        #pragma unroll
        for (int kk2 = 0; kk2 < 2; kk2++) {
            int k = bk + kk2 * 16;
            float4 v = *reinterpret_cast<const float4*>(B + (size_t)(k0 + k) * 64 + bn4 * 4);
            *reinterpret_cast<float4*>(&Bs[k][bn4 * 4]) = v;
        }
        __syncthreads();

        #pragma unroll
        for (int kk = 0; kk < 32; kk++) {
            float a[4], b[4];
            *reinterpret_cast<float4*>(a) = *reinterpret_cast<const float4*>(&As[kk][ty * 4]);
            *reinterpret_cast<float4*>(b) = *reinterpret_cast<const float4*>(&Bs[kk][tx * 4]);
            #pragma unroll
            for (int i = 0; i < 4; i++)
                #pragma unroll
                for (int j = 0; j < 4; j++)
                    acc[i][j] += a[i] * b[j];
        }
        __syncthreads();
    }

    #pragma unroll
    for (int i = 0; i < 4; i++) {
        int grow = rowBase + ty * 4 + i;
        if (grow < n) {
            *reinterpret_cast<float4*>(C + (size_t)grow * 64 + tx * 4) =
                make_float4(acc[i][0], acc[i][1], acc[i][2], acc[i][3]);
        }
    }
}

// ---------------- small GEMM: C[n x M] = A[n x K] @ B[K x M] ----------------
template <int K, int M>
__global__ __launch_bounds__(256) void gemm_small_kernel(
    const float* __restrict__ A, const float* __restrict__ B,
    float* __restrict__ C, int n)
{
    __shared__ float sW[K * (M + 1)];
    for (int i = threadIdx.x; i < K * M; i += blockDim.x)
        sW[(i / M) * (M + 1) + (i % M)] = B[i];
    __syncthreads();

    int t = blockIdx.x * blockDim.x + threadIdx.x;
    int row = t / M;
    int colm = t - row * M;
    if (row >= n) return;

    const float* a = A + (size_t)row * K;
    float acc = 0.f;
    #pragma unroll 16
    for (int k = 0; k < K; k++)
        acc += __ldg(a + k) * sW[k * (M + 1) + colm];
    C[(size_t)row * M + colm] = acc;
}

// ---------------- SpMM: out[i] = sum_{e in row i} val[e] * sup[col[e]] ----------------
template <int F>
__global__ __launch_bounds__(256) void spmm_kernel(
    const float* __restrict__ sup, const int* __restrict__ col,
    const float* __restrict__ val, float* __restrict__ out, int n)
{
    if constexpr (F == 64) {
        int gw = (blockIdx.x * blockDim.x + threadIdx.x) >> 5;
        int lane = threadIdx.x & 31;
        if (gw >= n) return;
        int e = g_rowptr[gw], eend = g_rowptr[gw + 1];
        float2 acc = make_float2(0.f, 0.f);
        const float2* s2 = reinterpret_cast<const float2*>(sup);
        #pragma unroll 4
        for (; e < eend; e++) {
            int   c = __ldg(col + e);
            float v = __ldg(val + e);
            float2 sv = __ldg(s2 + (size_t)c * 32 + lane);
            acc.x += v * sv.x;
            acc.y += v * sv.y;
        }
        reinterpret_cast<float2*>(out)[(size_t)gw * 32 + lane] = acc;
    } else if constexpr (F == 32) {
        int gw = (blockIdx.x * blockDim.x + threadIdx.x) >> 5;
        int lane = threadIdx.x & 31;
        if (gw >= n) return;
        int e = g_rowptr[gw], eend = g_rowptr[gw + 1];
        float acc = 0.f;
        #pragma unroll 4
        for (; e < eend; e++) {
            int   c = __ldg(col + e);
            float v = __ldg(val + e);
            acc += v * __ldg(sup + (size_t)c * 32 + lane);
        }
        out[(size_t)gw * 32 + lane] = acc;
    } else {  // F == 16, sub-warps of 16
        int gs = (blockIdx.x * blockDim.x + threadIdx.x) >> 4;
        int lane = threadIdx.x & 15;
        if (gs >= n) return;
        int e = g_rowptr[gs], eend = g_rowptr[gs + 1];
        float acc = 0.f;
        #pragma unroll 4
        for (; e < eend; e++) {
            int   c = __ldg(col + e);
            float v = __ldg(val + e);
            acc += v * __ldg(sup + (size_t)c * 16 + lane);
        }
        out[(size_t)gs * 16 + lane] = acc;
    }
}

// ---------------- final SpMM (F=40) fused with log_softmax -> d_out ----------------
__global__ __launch_bounds__(256) void spmm40_logsoftmax_kernel(
    const float* __restrict__ sup, const int* __restrict__ col,
    const float* __restrict__ val, float* __restrict__ out, int n)
{
    int gw = (blockIdx.x * blockDim.x + threadIdx.x) >> 5;
    int lane = threadIdx.x & 31;
    if (gw >= n) return;
    int e = g_rowptr[gw], eend = g_rowptr[gw + 1];
    bool second = (lane < 8);
    float a0 = 0.f, a1 = 0.f;
    #pragma unroll 2
    for (; e < eend; e++) {
        int   c = __ldg(col + e);
        float v = __ldg(val + e);
        a0 += v * __ldg(sup + (size_t)c * 40 + lane);
        if (second) a1 += v * __ldg(sup + (size_t)c * 40 + 32 + lane);
    }
    float m = a0;
    if (second) m = fmaxf(m, a1);
    #pragma unroll
    for (int off = 16; off > 0; off >>= 1)
        m = fmaxf(m, __shfl_xor_sync(0xffffffffu, m, off));
    float s = __expf(a0 - m);
    if (second) s += __expf(a1 - m);
    #pragma unroll
    for (int off = 16; off > 0; off >>= 1)
        s += __shfl_xor_sync(0xffffffffu, s, off);
    float lse = m + logf(s);
    out[(size_t)gw * 40 + lane] = a0 - lse;
    if (second) out[(size_t)gw * 40 + 32 + lane] = a1 - lse;
}

// ---------------- BN stats: sum & sumsq per feature ----------------
__global__ void zero_stats_kernel() {
    if (threadIdx.x < 128) g_stats[threadIdx.x] = 0.f;
}

template <int F>
__global__ __launch_bounds__(256) void bn_stats_kernel(const float* __restrict__ h, int n) {
    __shared__ float sm[512];
    int f = threadIdx.x % F;
    int rpb = 256 / F;
    int r = blockIdx.x * rpb + threadIdx.x / F;
    int stride = gridDim.x * rpb;
    float s = 0.f, ss = 0.f;
    for (; r < n; r += stride) {
        float v = h[(size_t)r * F + f];
        s += v;
        ss += v * v;
    }
    sm[threadIdx.x] = s;
    sm[256 + threadIdx.x] = ss;
    __syncthreads();
    for (int off = 128; off >= F; off >>= 1) {
        if (threadIdx.x < off) {
            sm[threadIdx.x]       += sm[threadIdx.x + off];
            sm[256 + threadIdx.x] += sm[256 + threadIdx.x + off];
        }
        __syncthreads();
    }
    if (threadIdx.x < F) {
        atomicAdd(&g_stats[threadIdx.x],      sm[threadIdx.x]);
        atomicAdd(&g_stats[64 + threadIdx.x], sm[256 + threadIdx.x]);
    }
}

// ---------------- BN apply + ELU (in place) ----------------
template <int F>
__global__ __launch_bounds__(256) void bn_elu_kernel(
    float* __restrict__ h, const float* __restrict__ gamma,
    const float* __restrict__ beta, int n)
{
    size_t total = (size_t)n * F;
    size_t idx = (size_t)blockIdx.x * blockDim.x + threadIdx.x;
    if (idx >= total) return;
    int f = (int)(idx % F);
    float invN = 1.f / (float)n;
    float mean = g_stats[f] * invN;
    float var  = g_stats[64 + f] * invN - mean * mean;
    float inv  = rsqrtf(var + BN_EPS);
    float v = (h[idx] - mean) * inv * __ldg(gamma + f) + __ldg(beta + f);
    h[idx] = (v > 0.f) ? v : expm1f(v);
}

// ---------------- launch ----------------
extern "C" void kernel_launch(void* const* d_in, const int* in_sizes, int n_in,
                              void* d_out, int out_size) {
    const float* x        = (const float*)d_in[0];
    const int*   edge_row = (const int*)  d_in[1];
    const int*   edge_col = (const int*)  d_in[2];
    const float* edge_val = (const float*)d_in[3];
    const float* W1 = (const float*)d_in[4];
    const float* W2 = (const float*)d_in[5];
    const float* W3 = (const float*)d_in[6];
    const float* W4 = (const float*)d_in[7];
    const float* g1 = (const float*)d_in[8];
    const float* b1 = (const float*)d_in[9];
    const float* g2 = (const float*)d_in[10];
    const float* b2 = (const float*)d_in[11];
    const float* g3 = (const float*)d_in[12];
    const float* b3 = (const float*)d_in[13];
    float* out = (float*)d_out;

    int n = in_sizes[0] / IN_DIM;   // 100000
    int e = in_sizes[1];            // 3200000

    float* sup1; cudaGetSymbolAddress((void**)&sup1, g_sup1);
    float* h1;   cudaGetSymbolAddress((void**)&h1,   g_h1);
    float* sup2; cudaGetSymbolAddress((void**)&sup2, g_sup2);
    float* h2;   cudaGetSymbolAddress((void**)&h2,   g_h2);
    float* sup3; cudaGetSymbolAddress((void**)&sup3, g_sup3);
    float* h3;   cudaGetSymbolAddress((void**)&h3,   g_h3);
    float* sup4; cudaGetSymbolAddress((void**)&sup4, g_sup4);

    // CSR row pointers from sorted edge_row
    build_rowptr_kernel<<<(e + 255) / 256, 256>>>(edge_row, n, e);

    // ---- layer 1 ----
    gemm512x64_kernel<<<(n + 63) / 64, 256>>>(x, W1, sup1, n);
    spmm_kernel<64><<<((size_t)n * 32 + 255) / 256, 256>>>(sup1, edge_col, edge_val, h1, n);
    zero_stats_kernel<<<1, 128>>>();
    bn_stats_kernel<64><<<240, 256>>>(h1, n);
    bn_elu_kernel<64><<<((size_t)n * 64 + 255) / 256, 256>>>(h1, g1, b1, n);

    // ---- layer 2 ----
    gemm_small_kernel<64, 32><<<((size_t)n * 32 + 255) / 256, 256>>>(h1, W2, sup2, n);
    spmm_kernel<32><<<((size_t)n * 32 + 255) / 256, 256>>>(sup2, edge_col, edge_val, h2, n);
    zero_stats_kernel<<<1, 128>>>();
    bn_stats_kernel<32><<<240, 256>>>(h2, n);
    bn_elu_kernel<32><<<((size_t)n * 32 + 255) / 256, 256>>>(h2, g2, b2, n);

    // ---- layer 3 ----
    gemm_small_kernel<32, 16><<<((size_t)n * 16 + 255) / 256, 256>>>(h2, W3, sup3, n);
    spmm_kernel<16><<<((size_t)n * 16 + 255) / 256, 256>>>(sup3, edge_col, edge_val, h3, n);
    zero_stats_kernel<<<1, 128>>>();
    bn_stats_kernel<16><<<240, 256>>>(h3, n);
    bn_elu_kernel<16><<<((size_t)n * 16 + 255) / 256, 256>>>(h3, g3, b3, n);

    // ---- layer 4 + log_softmax ----
    gemm_small_kernel<16, 40><<<((size_t)n * 40 + 255) / 256, 256>>>(h3, W4, sup4, n);
    spmm40_logsoftmax_kernel<<<((size_t)n * 32 + 255) / 256, 256>>>(sup4, edge_col, edge_val, out, n);
}